// round 1
// baseline (speedup 1.0000x reference)
#include <cuda_runtime.h>

#define DD 128
#define TILE_ROWS 128
#define STRIDE 132          // padded row stride (floats) for KU/Z and RT tiles
#define NTHREADS 256

// smem layout (floats):
//   Rrm  [128*128]        rotation row-major        (GEMM2 B operand)
//   RT   [128*STRIDE]     rotation transposed+pad   (GEMM1 B operand)
//   KU   [128*STRIDE]     normalized k tile; reused as Z between GEMMs
//   norms[128], scl[128], iscl[128], cb[16] (8 centroids + 7 boundaries)
#define SMEM_FLOATS (DD*DD + 2*TILE_ROWS*STRIDE + TILE_ROWS + 2*DD + 16)
#define SMEM_BYTES  (SMEM_FLOATS * 4)

__device__ __forceinline__ unsigned long long pack2(float x) {
    unsigned long long r;
    asm("mov.b64 %0, {%1, %1};" : "=l"(r) : "f"(x));
    return r;
}
__device__ __forceinline__ unsigned long long pack2b(float lo, float hi) {
    unsigned long long r;
    asm("mov.b64 %0, {%1, %2};" : "=l"(r) : "f"(lo), "f"(hi));
    return r;
}
__device__ __forceinline__ void unpack2(unsigned long long v, float &lo, float &hi) {
    asm("mov.b64 {%0, %1}, %2;" : "=f"(lo), "=f"(hi) : "l"(v));
}
// packed 2xf32 FMA: d = a*b + d  (FFMA2 — 2x scalar FFMA throughput on sm_103a)
__device__ __forceinline__ void ffma2(unsigned long long &d,
                                      unsigned long long a,
                                      unsigned long long b) {
    asm("fma.rn.f32x2 %0, %1, %2, %0;" : "+l"(d) : "l"(a), "l"(b));
}

__device__ __forceinline__ float quantize1(float v, const float* __restrict__ cc,
                                           const float* __restrict__ bn) {
    // searchsorted(side='left'): idx = #{bn < v}  ->  compare+select chain
    float z = cc[0];
    #pragma unroll
    for (int t = 0; t < 7; ++t) z = (v > bn[t]) ? cc[t + 1] : z;
    return z;
}

extern "C" __global__ void __launch_bounds__(NTHREADS, 1)
rotadapt_kernel(const float* __restrict__ k,
                const float* __restrict__ rot,
                const float* __restrict__ scales,
                const float* __restrict__ cent,
                float* __restrict__ out)
{
    extern __shared__ float sm[];
    float* Rrm     = sm;                         // 16384
    float* RT      = Rrm + DD * DD;              // 128*132
    float* KU      = RT + TILE_ROWS * STRIDE;    // 128*132 (reused as Z)
    float* norms_s = KU + TILE_ROWS * STRIDE;    // 128
    float* scl     = norms_s + TILE_ROWS;        // 128
    float* iscl    = scl + DD;                   // 128
    float* cb      = iscl + DD;                  // 16

    const int tid = threadIdx.x;

    // ---- prologue: rotation load (+ transpose with padded stride) ----
    #pragma unroll
    for (int it = 0; it < (DD * DD) / NTHREADS; ++it) {
        int idx = tid + it * NTHREADS;
        int j = idx >> 7;        // rotation row
        int i = idx & 127;       // rotation col
        float g = rot[idx];
        Rrm[idx] = g;
        RT[i * STRIDE + j] = g;  // RT[i][j] = rotation[j][i]
    }
    if (tid < DD) {
        float s = scales[tid];
        scl[tid]  = s;
        iscl[tid] = 1.0f / fmaxf(s, 1e-6f);
    }
    if (tid < 8) cb[tid] = cent[tid];
    if (tid < 7) cb[8 + tid] = 0.5f * (cent[tid] + cent[tid + 1]);

    // ---- load K tile, compute norms, write normalized (padded) KU ----
    const int w = tid >> 5, l = tid & 31;
    const long rowbase = (long)blockIdx.x * TILE_ROWS;
    const float4* k4 = (const float4*)k;
    #pragma unroll 2
    for (int m = 0; m < 16; ++m) {
        int r = w * 16 + m;
        float4 v = k4[(rowbase + r) * (DD / 4) + l];
        float ssq = v.x * v.x + v.y * v.y + v.z * v.z + v.w * v.w;
        #pragma unroll
        for (int off = 16; off; off >>= 1) ssq += __shfl_xor_sync(0xffffffffu, ssq, off);
        float nrm = sqrtf(ssq);
        float inv = 1.0f / (nrm + 1e-10f);
        if (l == 0) norms_s[r] = nrm;
        float4 kv = make_float4(v.x * inv, v.y * inv, v.z * inv, v.w * inv);
        *(float4*)&KU[r * STRIDE + 4 * l] = kv;
    }
    __syncthreads();

    const int tx = tid & 15, ty = tid >> 4;
    const int r0 = ty * 8, j0 = tx * 8;

    // ---- GEMM1: S[r][j] = sum_i KU[r][i] * RT[i][j], 8x8 per thread ----
    unsigned long long acc[8][4];
    #pragma unroll
    for (int u = 0; u < 8; ++u)
        #pragma unroll
        for (int p = 0; p < 4; ++p) acc[u][p] = 0ull;

    #pragma unroll 4
    for (int kk = 0; kk < DD; ++kk) {
        const ulonglong2* bp = (const ulonglong2*)&RT[kk * STRIDE + j0];
        ulonglong2 b01 = bp[0];
        ulonglong2 b23 = bp[1];
        unsigned long long bb0 = b01.x, bb1 = b01.y, bb2 = b23.x, bb3 = b23.y;
        #pragma unroll
        for (int u = 0; u < 8; ++u) {
            unsigned long long a2 = pack2(KU[(r0 + u) * STRIDE + kk]);
            ffma2(acc[u][0], a2, bb0);
            ffma2(acc[u][1], a2, bb1);
            ffma2(acc[u][2], a2, bb2);
            ffma2(acc[u][3], a2, bb3);
        }
    }

    // ---- epilogue 1: scale -> bucketize -> centroid -> inverse scale ----
    float scv[8], iscv[8];
    #pragma unroll
    for (int v = 0; v < 8; ++v) { scv[v] = scl[j0 + v]; iscv[v] = iscl[j0 + v]; }
    float cc[8], bn[7];
    #pragma unroll
    for (int t = 0; t < 8; ++t) cc[t] = cb[t];
    #pragma unroll
    for (int t = 0; t < 7; ++t) bn[t] = cb[8 + t];

    #pragma unroll
    for (int u = 0; u < 8; ++u) {
        #pragma unroll
        for (int p = 0; p < 4; ++p) {
            float f0, f1;
            unpack2(acc[u][p], f0, f1);
            int v0 = 2 * p, v1 = 2 * p + 1;
            f0 *= scv[v0];
            f1 *= scv[v1];
            float z0 = quantize1(f0, cc, bn) * iscv[v0];
            float z1 = quantize1(f1, cc, bn) * iscv[v1];
            acc[u][p] = pack2b(z0, z1);
        }
    }

    __syncthreads();  // everyone done reading KU before overwrite with Z
    #pragma unroll
    for (int u = 0; u < 8; ++u) {
        ulonglong2* zp = (ulonglong2*)&KU[(r0 + u) * STRIDE + j0];
        ulonglong2 z01; z01.x = acc[u][0]; z01.y = acc[u][1];
        ulonglong2 z23; z23.x = acc[u][2]; z23.y = acc[u][3];
        zp[0] = z01;
        zp[1] = z23;
    }
    __syncthreads();

    // ---- GEMM2: KH[r][i] = sum_j Z[r][j] * Rrm[j][i] ----
    #pragma unroll
    for (int u = 0; u < 8; ++u)
        #pragma unroll
        for (int p = 0; p < 4; ++p) acc[u][p] = 0ull;

    #pragma unroll 4
    for (int j = 0; j < DD; ++j) {
        const ulonglong2* bp = (const ulonglong2*)&Rrm[j * DD + j0];
        ulonglong2 b01 = bp[0];
        ulonglong2 b23 = bp[1];
        unsigned long long bb0 = b01.x, bb1 = b01.y, bb2 = b23.x, bb3 = b23.y;
        #pragma unroll
        for (int u = 0; u < 8; ++u) {
            unsigned long long a2 = pack2(KU[(r0 + u) * STRIDE + j]);
            ffma2(acc[u][0], a2, bb0);
            ffma2(acc[u][1], a2, bb1);
            ffma2(acc[u][2], a2, bb2);
            ffma2(acc[u][3], a2, bb3);
        }
    }

    // ---- epilogue 2: multiply by row norm, store coalesced float4 ----
    float4* out4 = (float4*)out;
    #pragma unroll
    for (int u = 0; u < 8; ++u) {
        float nr = norms_s[r0 + u];
        float h[8];
        #pragma unroll
        for (int p = 0; p < 4; ++p) {
            float f0, f1;
            unpack2(acc[u][p], f0, f1);
            h[2 * p]     = f0 * nr;
            h[2 * p + 1] = f1 * nr;
        }
        long orow = (rowbase + r0 + u) * (DD / 4) + tx * 2;
        out4[orow]     = make_float4(h[0], h[1], h[2], h[3]);
        out4[orow + 1] = make_float4(h[4], h[5], h[6], h[7]);
    }
}

extern "C" void kernel_launch(void* const* d_in, const int* in_sizes, int n_in,
                              void* d_out, int out_size) {
    const float* k      = (const float*)d_in[0];
    const float* rot    = (const float*)d_in[1];
    const float* scales = (const float*)d_in[2];
    const float* cent   = (const float*)d_in[3];
    float* out = (float*)d_out;

    int nrows = in_sizes[0] / DD;
    int nblocks = nrows / TILE_ROWS;  // N = 1048576 -> 8192 tiles exactly

    cudaFuncSetAttribute(rotadapt_kernel,
                         cudaFuncAttributeMaxDynamicSharedMemorySize, SMEM_BYTES);
    rotadapt_kernel<<<nblocks, NTHREADS, SMEM_BYTES>>>(k, rot, scales, cent, out);
}

// round 2
// speedup vs baseline: 1.0015x; 1.0015x over previous
#include <cuda_runtime.h>

#define DD 128
#define TILE_ROWS 128
#define STRIDE 132          // padded row stride (floats) for KU/Z and RT tiles
#define NTHREADS 256

// smem layout (floats):
//   Rrm  [128*128]        rotation row-major        (GEMM2 B operand)
//   RT   [128*STRIDE]     rotation transposed+pad   (GEMM1 B operand)
//   KU   [128*STRIDE]     normalized k tile; reused as Z between GEMMs
//   norms[128], scl[128], iscl[128], cb[16] (8 centroids + 7 boundaries)
#define SMEM_FLOATS (DD*DD + 2*TILE_ROWS*STRIDE + TILE_ROWS + 2*DD + 16)
#define SMEM_BYTES  (SMEM_FLOATS * 4)

__device__ __forceinline__ unsigned long long pack2(float x) {
    unsigned long long r;
    asm("mov.b64 %0, {%1, %1};" : "=l"(r) : "f"(x));
    return r;
}
__device__ __forceinline__ unsigned long long pack2b(float lo, float hi) {
    unsigned long long r;
    asm("mov.b64 %0, {%1, %2};" : "=l"(r) : "f"(lo), "f"(hi));
    return r;
}
__device__ __forceinline__ void unpack2(unsigned long long v, float &lo, float &hi) {
    asm("mov.b64 {%0, %1}, %2;" : "=f"(lo), "=f"(hi) : "l"(v));
}
// packed 2xf32 FMA: d = a*b + d  (FFMA2 — 2x scalar FFMA throughput on sm_103a)
__device__ __forceinline__ void ffma2(unsigned long long &d,
                                      unsigned long long a,
                                      unsigned long long b) {
    asm("fma.rn.f32x2 %0, %1, %2, %0;" : "+l"(d) : "l"(a), "l"(b));
}

__device__ __forceinline__ float quantize1(float v, const float* __restrict__ cc,
                                           const float* __restrict__ bn) {
    // searchsorted(side='left'): idx = #{bn < v}  ->  compare+select chain
    float z = cc[0];
    #pragma unroll
    for (int t = 0; t < 7; ++t) z = (v > bn[t]) ? cc[t + 1] : z;
    return z;
}

extern "C" __global__ void __launch_bounds__(NTHREADS, 1)
rotadapt_kernel(const float* __restrict__ k,
                const float* __restrict__ rot,
                const float* __restrict__ scales,
                const float* __restrict__ cent,
                float* __restrict__ out)
{
    extern __shared__ float sm[];
    float* Rrm     = sm;                         // 16384
    float* RT      = Rrm + DD * DD;              // 128*132
    float* KU      = RT + TILE_ROWS * STRIDE;    // 128*132 (reused as Z)
    float* norms_s = KU + TILE_ROWS * STRIDE;    // 128
    float* scl     = norms_s + TILE_ROWS;        // 128
    float* iscl    = scl + DD;                   // 128
    float* cb      = iscl + DD;                  // 16

    const int tid = threadIdx.x;

    // ---- prologue: rotation load (+ transpose with padded stride) ----
    #pragma unroll
    for (int it = 0; it < (DD * DD) / NTHREADS; ++it) {
        int idx = tid + it * NTHREADS;
        int j = idx >> 7;        // rotation row
        int i = idx & 127;       // rotation col
        float g = rot[idx];
        Rrm[idx] = g;
        RT[i * STRIDE + j] = g;  // RT[i][j] = rotation[j][i]
    }
    if (tid < DD) {
        float s = scales[tid];
        scl[tid]  = s;
        iscl[tid] = 1.0f / fmaxf(s, 1e-6f);
    }
    if (tid < 8) cb[tid] = cent[tid];
    if (tid < 7) cb[8 + tid] = 0.5f * (cent[tid] + cent[tid + 1]);

    // ---- load K tile, compute norms, write normalized (padded) KU ----
    const int w = tid >> 5, l = tid & 31;
    const long rowbase = (long)blockIdx.x * TILE_ROWS;
    const float4* k4 = (const float4*)k;
    #pragma unroll 2
    for (int m = 0; m < 16; ++m) {
        int r = w * 16 + m;
        float4 v = k4[(rowbase + r) * (DD / 4) + l];
        float ssq = v.x * v.x + v.y * v.y + v.z * v.z + v.w * v.w;
        #pragma unroll
        for (int off = 16; off; off >>= 1) ssq += __shfl_xor_sync(0xffffffffu, ssq, off);
        float nrm = sqrtf(ssq);
        float inv = 1.0f / (nrm + 1e-10f);
        if (l == 0) norms_s[r] = nrm;
        float4 kv = make_float4(v.x * inv, v.y * inv, v.z * inv, v.w * inv);
        *(float4*)&KU[r * STRIDE + 4 * l] = kv;
    }
    __syncthreads();

    const int tx = tid & 15, ty = tid >> 4;
    const int r0 = ty * 8, j0 = tx * 8;

    // ---- GEMM1: S[r][j] = sum_i KU[r][i] * RT[i][j], 8x8 per thread ----
    unsigned long long acc[8][4];
    #pragma unroll
    for (int u = 0; u < 8; ++u)
        #pragma unroll
        for (int p = 0; p < 4; ++p) acc[u][p] = 0ull;

    #pragma unroll 4
    for (int kk = 0; kk < DD; ++kk) {
        const ulonglong2* bp = (const ulonglong2*)&RT[kk * STRIDE + j0];
        ulonglong2 b01 = bp[0];
        ulonglong2 b23 = bp[1];
        unsigned long long bb0 = b01.x, bb1 = b01.y, bb2 = b23.x, bb3 = b23.y;
        #pragma unroll
        for (int u = 0; u < 8; ++u) {
            unsigned long long a2 = pack2(KU[(r0 + u) * STRIDE + kk]);
            ffma2(acc[u][0], a2, bb0);
            ffma2(acc[u][1], a2, bb1);
            ffma2(acc[u][2], a2, bb2);
            ffma2(acc[u][3], a2, bb3);
        }
    }

    // ---- epilogue 1: scale -> bucketize -> centroid -> inverse scale ----
    float scv[8], iscv[8];
    #pragma unroll
    for (int v = 0; v < 8; ++v) { scv[v] = scl[j0 + v]; iscv[v] = iscl[j0 + v]; }
    float cc[8], bn[7];
    #pragma unroll
    for (int t = 0; t < 8; ++t) cc[t] = cb[t];
    #pragma unroll
    for (int t = 0; t < 7; ++t) bn[t] = cb[8 + t];

    #pragma unroll
    for (int u = 0; u < 8; ++u) {
        #pragma unroll
        for (int p = 0; p < 4; ++p) {
            float f0, f1;
            unpack2(acc[u][p], f0, f1);
            int v0 = 2 * p, v1 = 2 * p + 1;
            f0 *= scv[v0];
            f1 *= scv[v1];
            float z0 = quantize1(f0, cc, bn) * iscv[v0];
            float z1 = quantize1(f1, cc, bn) * iscv[v1];
            acc[u][p] = pack2b(z0, z1);
        }
    }

    __syncthreads();  // everyone done reading KU before overwrite with Z
    #pragma unroll
    for (int u = 0; u < 8; ++u) {
        ulonglong2* zp = (ulonglong2*)&KU[(r0 + u) * STRIDE + j0];
        ulonglong2 z01; z01.x = acc[u][0]; z01.y = acc[u][1];
        ulonglong2 z23; z23.x = acc[u][2]; z23.y = acc[u][3];
        zp[0] = z01;
        zp[1] = z23;
    }
    __syncthreads();

    // ---- GEMM2: KH[r][i] = sum_j Z[r][j] * Rrm[j][i] ----
    #pragma unroll
    for (int u = 0; u < 8; ++u)
        #pragma unroll
        for (int p = 0; p < 4; ++p) acc[u][p] = 0ull;

    #pragma unroll 4
    for (int j = 0; j < DD; ++j) {
        const ulonglong2* bp = (const ulonglong2*)&Rrm[j * DD + j0];
        ulonglong2 b01 = bp[0];
        ulonglong2 b23 = bp[1];
        unsigned long long bb0 = b01.x, bb1 = b01.y, bb2 = b23.x, bb3 = b23.y;
        #pragma unroll
        for (int u = 0; u < 8; ++u) {
            unsigned long long a2 = pack2(KU[(r0 + u) * STRIDE + j]);
            ffma2(acc[u][0], a2, bb0);
            ffma2(acc[u][1], a2, bb1);
            ffma2(acc[u][2], a2, bb2);
            ffma2(acc[u][3], a2, bb3);
        }
    }

    // ---- epilogue 2: multiply by row norm, store coalesced float4 ----
    float4* out4 = (float4*)out;
    #pragma unroll
    for (int u = 0; u < 8; ++u) {
        float nr = norms_s[r0 + u];
        float h[8];
        #pragma unroll
        for (int p = 0; p < 4; ++p) {
            float f0, f1;
            unpack2(acc[u][p], f0, f1);
            h[2 * p]     = f0 * nr;
            h[2 * p + 1] = f1 * nr;
        }
        long orow = (rowbase + r0 + u) * (DD / 4) + tx * 2;
        out4[orow]     = make_float4(h[0], h[1], h[2], h[3]);
        out4[orow + 1] = make_float4(h[4], h[5], h[6], h[7]);
    }
}

extern "C" void kernel_launch(void* const* d_in, const int* in_sizes, int n_in,
                              void* d_out, int out_size) {
    const float* k      = (const float*)d_in[0];
    const float* rot    = (const float*)d_in[1];
    const float* scales = (const float*)d_in[2];
    const float* cent   = (const float*)d_in[3];
    float* out = (float*)d_out;

    int nrows = in_sizes[0] / DD;
    int nblocks = nrows / TILE_ROWS;  // N = 1048576 -> 8192 tiles exactly

    cudaFuncSetAttribute(rotadapt_kernel,
                         cudaFuncAttributeMaxDynamicSharedMemorySize, SMEM_BYTES);
    rotadapt_kernel<<<nblocks, NTHREADS, SMEM_BYTES>>>(k, rot, scales, cent, out);
}

// round 3
// speedup vs baseline: 1.0212x; 1.0197x over previous
#include <cuda_runtime.h>

#define DD 128
#define TILE_ROWS 128
#define STRIDE 132          // padded row stride (floats) for KU/Z and RT tiles
#define NTHREADS 256

// smem layout (floats):
//   Rrm  [128*128]        rotation row-major        (GEMM2 B operand)
//   RT   [128*STRIDE]     rotation transposed+pad   (GEMM1 B operand)
//   KU   [128*STRIDE]     normalized k tile; reused as Z between GEMMs
//   norms[128], scl[128], iscl[128], cb[16]
#define SMEM_FLOATS (DD*DD + 2*TILE_ROWS*STRIDE + TILE_ROWS + 2*DD + 16)
#define SMEM_BYTES  (SMEM_FLOATS * 4)

__device__ __forceinline__ unsigned long long pack2(float x) {
    unsigned long long r;
    asm("mov.b64 %0, {%1, %1};" : "=l"(r) : "f"(x));
    return r;
}
__device__ __forceinline__ unsigned long long pack2b(float lo, float hi) {
    unsigned long long r;
    asm("mov.b64 %0, {%1, %2};" : "=l"(r) : "f"(lo), "f"(hi));
    return r;
}
__device__ __forceinline__ void unpack2(unsigned long long v, float &lo, float &hi) {
    asm("mov.b64 {%0, %1}, %2;" : "=f"(lo), "=f"(hi) : "l"(v));
}
// packed 2xf32 FMA: d = a*b + d  (FFMA2 — 2x scalar FFMA throughput on sm_103a)
__device__ __forceinline__ void ffma2(unsigned long long &d,
                                      unsigned long long a,
                                      unsigned long long b) {
    asm("fma.rn.f32x2 %0, %1, %2, %0;" : "+l"(d) : "l"(a), "l"(b));
}

__device__ __forceinline__ float quantize1(float v, const float* __restrict__ cc,
                                           const float* __restrict__ bn) {
    // searchsorted(side='left'): idx = #{bn < v}  ->  compare+select chain
    float z = cc[0];
    #pragma unroll
    for (int t = 0; t < 7; ++t) z = (v > bn[t]) ? cc[t + 1] : z;
    return z;
}

extern "C" __global__ void __launch_bounds__(NTHREADS, 1)
rotadapt_kernel(const float* __restrict__ k,
                const float* __restrict__ rot,
                const float* __restrict__ scales,
                const float* __restrict__ cent,
                float* __restrict__ out)
{
    extern __shared__ float sm[];
    float* Rrm     = sm;                         // 16384
    float* RT      = Rrm + DD * DD;              // 128*132
    float* KU      = RT + TILE_ROWS * STRIDE;    // 128*132 (reused as Z)
    float* norms_s = KU + TILE_ROWS * STRIDE;    // 128
    float* scl     = norms_s + TILE_ROWS;        // 128
    float* iscl    = scl + DD;                   // 128
    float* cb      = iscl + DD;                  // 16

    const int tid = threadIdx.x;

    // ---- prologue: rotation load (+ transpose with padded stride) ----
    #pragma unroll
    for (int it = 0; it < (DD * DD) / NTHREADS; ++it) {
        int idx = tid + it * NTHREADS;
        int j = idx >> 7;        // rotation row
        int i = idx & 127;       // rotation col
        float g = rot[idx];
        Rrm[idx] = g;
        RT[i * STRIDE + j] = g;  // RT[i][j] = rotation[j][i]
    }
    if (tid < DD) {
        float s = scales[tid];
        scl[tid]  = s;
        iscl[tid] = 1.0f / fmaxf(s, 1e-6f);
    }
    if (tid < 8) cb[tid] = cent[tid];
    if (tid < 7) cb[8 + tid] = 0.5f * (cent[tid] + cent[tid + 1]);

    // ---- load K tile, compute norms, write normalized (padded) KU ----
    const int w = tid >> 5, l = tid & 31;
    const long rowbase = (long)blockIdx.x * TILE_ROWS;
    const float4* k4 = (const float4*)k;
    #pragma unroll 2
    for (int m = 0; m < 16; ++m) {
        int r = w * 16 + m;
        float4 v = k4[(rowbase + r) * (DD / 4) + l];
        float ssq = v.x * v.x + v.y * v.y + v.z * v.z + v.w * v.w;
        #pragma unroll
        for (int off = 16; off; off >>= 1) ssq += __shfl_xor_sync(0xffffffffu, ssq, off);
        float nrm = sqrtf(ssq);
        float inv = 1.0f / (nrm + 1e-10f);
        if (l == 0) norms_s[r] = nrm;
        float4 kv = make_float4(v.x * inv, v.y * inv, v.z * inv, v.w * inv);
        *(float4*)&KU[r * STRIDE + 4 * l] = kv;
    }
    __syncthreads();

    const int tx = tid & 15, ty = tid >> 4;
    const int r0 = ty * 8, j0 = tx * 8;

    // ---- GEMM1: S[r][j] = sum_i KU[r][i] * RT[i][j], 8x8 per thread ----
    // k-blocked by 4: batch 8 A-float4 + 4 B-rows, then 128 FFMA2 (latency hiding)
    unsigned long long acc[8][4];
    #pragma unroll
    for (int u = 0; u < 8; ++u)
        #pragma unroll
        for (int p = 0; p < 4; ++p) acc[u][p] = 0ull;

    #pragma unroll 4
    for (int kb = 0; kb < DD; kb += 4) {
        float4 a4[8];
        #pragma unroll
        for (int u = 0; u < 8; ++u)
            a4[u] = *(const float4*)&KU[(r0 + u) * STRIDE + kb];
        unsigned long long bb[4][4];
        #pragma unroll
        for (int m = 0; m < 4; ++m) {
            const ulonglong2* bp = (const ulonglong2*)&RT[(kb + m) * STRIDE + j0];
            ulonglong2 b01 = bp[0];
            ulonglong2 b23 = bp[1];
            bb[m][0] = b01.x; bb[m][1] = b01.y; bb[m][2] = b23.x; bb[m][3] = b23.y;
        }
        #pragma unroll
        for (int m = 0; m < 4; ++m) {
            #pragma unroll
            for (int u = 0; u < 8; ++u) {
                float av = (m == 0) ? a4[u].x : (m == 1) ? a4[u].y
                         : (m == 2) ? a4[u].z : a4[u].w;
                unsigned long long a2 = pack2(av);
                ffma2(acc[u][0], a2, bb[m][0]);
                ffma2(acc[u][1], a2, bb[m][1]);
                ffma2(acc[u][2], a2, bb[m][2]);
                ffma2(acc[u][3], a2, bb[m][3]);
            }
        }
    }

    // ---- epilogue 1: scale -> bucketize -> centroid -> inverse scale ----
    float scv[8], iscv[8];
    #pragma unroll
    for (int v = 0; v < 8; ++v) { scv[v] = scl[j0 + v]; iscv[v] = iscl[j0 + v]; }
    float cc[8], bn[7];
    #pragma unroll
    for (int t = 0; t < 8; ++t) cc[t] = cb[t];
    #pragma unroll
    for (int t = 0; t < 7; ++t) bn[t] = cb[8 + t];

    #pragma unroll
    for (int u = 0; u < 8; ++u) {
        #pragma unroll
        for (int p = 0; p < 4; ++p) {
            float f0, f1;
            unpack2(acc[u][p], f0, f1);
            int v0 = 2 * p, v1 = 2 * p + 1;
            f0 *= scv[v0];
            f1 *= scv[v1];
            float z0 = quantize1(f0, cc, bn) * iscv[v0];
            float z1 = quantize1(f1, cc, bn) * iscv[v1];
            acc[u][p] = pack2b(z0, z1);
        }
    }

    __syncthreads();  // everyone done reading KU before overwrite with Z
    #pragma unroll
    for (int u = 0; u < 8; ++u) {
        ulonglong2* zp = (ulonglong2*)&KU[(r0 + u) * STRIDE + j0];
        ulonglong2 z01; z01.x = acc[u][0]; z01.y = acc[u][1];
        ulonglong2 z23; z23.x = acc[u][2]; z23.y = acc[u][3];
        zp[0] = z01;
        zp[1] = z23;
    }
    __syncthreads();

    // ---- GEMM2: KH[r][i] = sum_j Z[r][j] * Rrm[j][i], same k-blocked scheme ----
    #pragma unroll
    for (int u = 0; u < 8; ++u)
        #pragma unroll
        for (int p = 0; p < 4; ++p) acc[u][p] = 0ull;

    #pragma unroll 4
    for (int jb = 0; jb < DD; jb += 4) {
        float4 a4[8];
        #pragma unroll
        for (int u = 0; u < 8; ++u)
            a4[u] = *(const float4*)&KU[(r0 + u) * STRIDE + jb];
        unsigned long long bb[4][4];
        #pragma unroll
        for (int m = 0; m < 4; ++m) {
            const ulonglong2* bp = (const ulonglong2*)&Rrm[(jb + m) * DD + j0];
            ulonglong2 b01 = bp[0];
            ulonglong2 b23 = bp[1];
            bb[m][0] = b01.x; bb[m][1] = b01.y; bb[m][2] = b23.x; bb[m][3] = b23.y;
        }
        #pragma unroll
        for (int m = 0; m < 4; ++m) {
            #pragma unroll
            for (int u = 0; u < 8; ++u) {
                float av = (m == 0) ? a4[u].x : (m == 1) ? a4[u].y
                         : (m == 2) ? a4[u].z : a4[u].w;
                unsigned long long a2 = pack2(av);
                ffma2(acc[u][0], a2, bb[m][0]);
                ffma2(acc[u][1], a2, bb[m][1]);
                ffma2(acc[u][2], a2, bb[m][2]);
                ffma2(acc[u][3], a2, bb[m][3]);
            }
        }
    }

    // ---- epilogue 2: multiply by row norm, store coalesced float4 ----
    float4* out4 = (float4*)out;
    #pragma unroll
    for (int u = 0; u < 8; ++u) {
        float nr = norms_s[r0 + u];
        float h[8];
        #pragma unroll
        for (int p = 0; p < 4; ++p) {
            float f0, f1;
            unpack2(acc[u][p], f0, f1);
            h[2 * p]     = f0 * nr;
            h[2 * p + 1] = f1 * nr;
        }
        long orow = (rowbase + r0 + u) * (DD / 4) + tx * 2;
        out4[orow]     = make_float4(h[0], h[1], h[2], h[3]);
        out4[orow + 1] = make_float4(h[4], h[5], h[6], h[7]);
    }
}

extern "C" void kernel_launch(void* const* d_in, const int* in_sizes, int n_in,
                              void* d_out, int out_size) {
    const float* k      = (const float*)d_in[0];
    const float* rot    = (const float*)d_in[1];
    const float* scales = (const float*)d_in[2];
    const float* cent   = (const float*)d_in[3];
    float* out = (float*)d_out;

    int nrows = in_sizes[0] / DD;
    int nblocks = nrows / TILE_ROWS;  // N = 1048576 -> 8192 tiles exactly

    cudaFuncSetAttribute(rotadapt_kernel,
                         cudaFuncAttributeMaxDynamicSharedMemorySize, SMEM_BYTES);
    rotadapt_kernel<<<nblocks, NTHREADS, SMEM_BYTES>>>(k, rot, scales, cent, out);
}

// round 5
// speedup vs baseline: 1.8184x; 1.7806x over previous
#include <cuda_runtime.h>
#include <cstdint>

#define DD 128
#define NTILES 4
#define NTHREADS 256

// ---- smem byte offsets ----
#define SM_B1HI 0           // R hi, fragment-packed: frag(ks,nt)*32 lanes * float2
#define SM_B1LO 65536       // R lo, same packing
#define SM_ZI   131072      // quantized indices: 128 rows x 132 bytes
#define SM_NRM  147968      // 128 f32
#define SM_INV  148480      // 128 f32
#define SM_SCL  148992      // 128 f32
#define SM_ISCL 149504      // 128 f32
#define SM_PART 150016      // 256 f32
#define SMEM_BYTES 151040

__device__ __forceinline__ uint32_t tf32u(float x) {
    uint32_t r;
    asm("cvt.rna.tf32.f32 %0, %1;" : "=r"(r) : "f"(x));
    return r;
}

// D += A(tf32) * B(tf32), m16n8k8, fp32 accumulate
__device__ __forceinline__ void mma8(float d[4], const uint32_t a[4],
                                     uint32_t b0, uint32_t b1) {
    asm volatile(
        "mma.sync.aligned.m16n8k8.row.col.f32.tf32.tf32.f32 "
        "{%0,%1,%2,%3}, {%4,%5,%6,%7}, {%8,%9}, {%0,%1,%2,%3};"
        : "+f"(d[0]), "+f"(d[1]), "+f"(d[2]), "+f"(d[3])
        : "r"(a[0]), "r"(a[1]), "r"(a[2]), "r"(a[3]), "r"(b0), "r"(b1));
}

extern "C" __global__ void __launch_bounds__(NTHREADS, 1)
rotadapt_mma_kernel(const float* __restrict__ k,
                    const float* __restrict__ rot,
                    const float* __restrict__ scales,
                    const float* __restrict__ cent,
                    float* __restrict__ out)
{
    extern __shared__ char sb[];
    float* sclp  = (float*)(sb + SM_SCL);
    float* isclp = (float*)(sb + SM_ISCL);
    float* nrmp  = (float*)(sb + SM_NRM);
    float* invp  = (float*)(sb + SM_INV);
    float* partp = (float*)(sb + SM_PART);

    const int tid  = threadIdx.x;
    const int lane = tid & 31, w = tid >> 5;
    const int g = lane >> 2, t = lane & 3;
    const int r1 = 16 * w + g, r2 = r1 + 8;

    // ---- prologue: pack R into hi/lo fragment layout ----
    // frag(ks,nt) float2 index = (ks*16+nt)*32 + lane; b0=R[8nt+g][8ks+t], b1=...[8ks+t+4]
    for (int idx = tid; idx < DD * DD; idx += NTHREADS) {
        int j = idx >> 7, i = idx & 127;     // R[j][i] = rot[j*128+i]
        float v = rot[idx];
        uint32_t hu = tf32u(v);
        float lo = v - __uint_as_float(hu);
        uint32_t lu = tf32u(lo);
        int fi = (((i >> 3) * 16 + (j >> 3)) * 32 + (j & 7) * 4 + (i & 3)) * 2
                 + ((i >> 2) & 1);
        ((uint32_t*)(sb + SM_B1HI))[fi] = hu;
        ((uint32_t*)(sb + SM_B1LO))[fi] = lu;
    }
    if (tid < DD) {
        float s = scales[tid];
        sclp[tid]  = s;
        isclp[tid] = 1.0f / fmaxf(s, 1e-6f);
    }
    __syncthreads();

    // per-thread constants
    float bn[7];
    #pragma unroll
    for (int q = 0; q < 7; ++q) bn[q] = 0.5f * (cent[q] + cent[q + 1]);
    const float ccv = cent[lane & 7];    // centroid table distributed over lanes 0-7

    const float2* bh2 = (const float2*)(sb + SM_B1HI);
    const float2* bl2 = (const float2*)(sb + SM_B1LO);
    const float*  bhf = (const float*)(sb + SM_B1HI);
    char* zi = sb + SM_ZI;

    const long tile0 = (long)blockIdx.x * NTILES;

    for (int tt = 0; tt < NTILES; ++tt) {
        const long rowbase = (tile0 + tt) * DD;

        // ---- phase A: row norms (also warms L1 with this tile's k) ----
        {
            const int m = tid & 127, h = tid >> 7;
            const float4* kp = (const float4*)(k + (rowbase + m) * (long)DD + h * 64);
            float ssq = 0.0f;
            #pragma unroll
            for (int j = 0; j < 16; ++j) {
                float4 v = kp[j];
                ssq += v.x * v.x + v.y * v.y + v.z * v.z + v.w * v.w;
            }
            partp[h * 128 + m] = ssq;
            __syncthreads();
            if (h == 0) {
                float nr = sqrtf(partp[m] + partp[128 + m]);
                nrmp[m] = nr;
                invp[m] = 1.0f / (nr + 1e-10f);
            }
            __syncthreads();
        }

        // ---- GEMM1 (3-pass tf32): shaped_pre = KU @ R^T ----
        float acc[16][4];
        #pragma unroll
        for (int nt = 0; nt < 16; ++nt)
            #pragma unroll
            for (int p = 0; p < 4; ++p) acc[nt][p] = 0.0f;

        {
            const float inv1 = invp[r1], inv2 = invp[r2];
            const float* k1 = k + (rowbase + r1) * (long)DD;
            const float* k2 = k + (rowbase + r2) * (long)DD;
            #pragma unroll 2
            for (int ks = 0; ks < 16; ++ks) {
                float f0 = k1[8 * ks + t]     * inv1;
                float f1 = k2[8 * ks + t]     * inv2;
                float f2 = k1[8 * ks + t + 4] * inv1;
                float f3 = k2[8 * ks + t + 4] * inv2;
                uint32_t ah[4], al[4];
                ah[0] = tf32u(f0); al[0] = tf32u(f0 - __uint_as_float(ah[0]));
                ah[1] = tf32u(f1); al[1] = tf32u(f1 - __uint_as_float(ah[1]));
                ah[2] = tf32u(f2); al[2] = tf32u(f2 - __uint_as_float(ah[2]));
                ah[3] = tf32u(f3); al[3] = tf32u(f3 - __uint_as_float(ah[3]));
                #pragma unroll
                for (int nt = 0; nt < 16; ++nt) {
                    int fi = (ks * 16 + nt) * 32 + lane;
                    float2 bh = bh2[fi];
                    float2 bl = bl2[fi];
                    uint32_t bh0 = __float_as_uint(bh.x), bh1 = __float_as_uint(bh.y);
                    mma8(acc[nt], ah, bh0, bh1);
                    mma8(acc[nt], al, bh0, bh1);
                    mma8(acc[nt], ah, __float_as_uint(bl.x), __float_as_uint(bl.y));
                }
            }
        }

        // ---- prefetch next tile's k into L1 (current tile's k no longer needed) ----
        if (tt + 1 < NTILES) {
            const char* np = (const char*)(k + (rowbase + DD) * (long)DD);
            asm volatile("prefetch.global.L1 [%0];" :: "l"(np + tid * 128));
            asm volatile("prefetch.global.L1 [%0];" :: "l"(np + (NTHREADS + tid) * 128));
        }

        // ---- epilogue 1: scale -> bucketize -> store 3-bit indices ----
        {
            const float2* scl2 = (const float2*)(sb + SM_SCL);
            #pragma unroll
            for (int nt = 0; nt < 16; ++nt) {
                float2 sc = scl2[(8 * nt + 2 * t) >> 1];
                float f0 = acc[nt][0] * sc.x, f1 = acc[nt][1] * sc.y;
                float f2 = acc[nt][2] * sc.x, f3 = acc[nt][3] * sc.y;
                int i0 = 0, i1 = 0, i2 = 0, i3 = 0;
                #pragma unroll
                for (int q = 0; q < 7; ++q) {
                    i0 += (f0 > bn[q]); i1 += (f1 > bn[q]);
                    i2 += (f2 > bn[q]); i3 += (f3 > bn[q]);
                }
                // c0,c1 -> row r1 cols 8nt+2t,+1 ; c2,c3 -> row r2
                *(uint16_t*)(zi + r1 * 132 + 8 * nt + 2 * t) = (uint16_t)(i0 | (i1 << 8));
                *(uint16_t*)(zi + r2 * 132 + 8 * nt + 2 * t) = (uint16_t)(i2 | (i3 << 8));
            }
        }
        __syncwarp();   // GEMM2 A-frags read only this warp's ZI rows

        // ---- GEMM2 (2-pass tf32): k_hat_pre = Z @ R (B frags remapped from B1hi) ----
        float acc2[16][4];
        #pragma unroll
        for (int nt = 0; nt < 16; ++nt)
            #pragma unroll
            for (int p = 0; p < 4; ++p) acc2[nt][p] = 0.0f;

        {
            #pragma unroll 2
            for (int ks = 0; ks < 16; ++ks) {
                uint32_t wa = *(const uint32_t*)(zi + r1 * 132 + 8 * ks);
                uint32_t wb = *(const uint32_t*)(zi + r1 * 132 + 8 * ks + 4);
                uint32_t wc = *(const uint32_t*)(zi + r2 * 132 + 8 * ks);
                uint32_t wd = *(const uint32_t*)(zi + r2 * 132 + 8 * ks + 4);
                int sh = 8 * t;
                float c0 = __shfl_sync(0xffffffffu, ccv, (wa >> sh) & 0xff);
                float c1 = __shfl_sync(0xffffffffu, ccv, (wc >> sh) & 0xff);
                float c2 = __shfl_sync(0xffffffffu, ccv, (wb >> sh) & 0xff);
                float c3 = __shfl_sync(0xffffffffu, ccv, (wd >> sh) & 0xff);
                float is0 = isclp[8 * ks + t], is1 = isclp[8 * ks + t + 4];
                float z0 = c0 * is0, z1 = c1 * is0, z2 = c2 * is1, z3 = c3 * is1;
                uint32_t zh[4], zl[4];
                zh[0] = tf32u(z0); zl[0] = tf32u(z0 - __uint_as_float(zh[0]));
                zh[1] = tf32u(z1); zl[1] = tf32u(z1 - __uint_as_float(zh[1]));
                zh[2] = tf32u(z2); zl[2] = tf32u(z2 - __uint_as_float(zh[2]));
                zh[3] = tf32u(z3); zl[3] = tf32u(z3 - __uint_as_float(zh[3]));
                #pragma unroll
                for (int nt = 0; nt < 16; ++nt) {
                    // B2 frag(ks,nt) lane(g,t) lives in B1hi packed at remapped address
                    int base = ((nt * 16 + ks) * 32 + t * 4 + (g & 3)) * 2 + (g >> 2);
                    uint32_t b0 = __float_as_uint(bhf[base]);
                    uint32_t b1 = __float_as_uint(bhf[base + 32]);
                    mma8(acc2[nt], zh, b0, b1);
                    mma8(acc2[nt], zl, b0, b1);
                }
            }
        }

        // ---- epilogue 2: x norm, store ----
        {
            float nrm1 = nrmp[r1], nrm2 = nrmp[r2];
            float* o1 = out + (rowbase + r1) * (long)DD;
            float* o2 = out + (rowbase + r2) * (long)DD;
            #pragma unroll
            for (int nt = 0; nt < 16; ++nt) {
                int c = 8 * nt + 2 * t;
                *(float2*)(o1 + c) = make_float2(acc2[nt][0] * nrm1, acc2[nt][1] * nrm1);
                *(float2*)(o2 + c) = make_float2(acc2[nt][2] * nrm2, acc2[nt][3] * nrm2);
            }
        }
        // next tile's phase-A __syncthreads orders ZI/nrm reuse
    }
}

extern "C" void kernel_launch(void* const* d_in, const int* in_sizes, int n_in,
                              void* d_out, int out_size) {
    const float* k      = (const float*)d_in[0];
    const float* rot    = (const float*)d_in[1];
    const float* scales = (const float*)d_in[2];
    const float* cent   = (const float*)d_in[3];
    float* out = (float*)d_out;

    int nrows = in_sizes[0] / DD;
    int nblocks = nrows / (DD * NTILES);   // 1048576/128 = 8192 tiles -> 2048 CTAs

    cudaFuncSetAttribute(rotadapt_mma_kernel,
                         cudaFuncAttributeMaxDynamicSharedMemorySize, SMEM_BYTES);
    rotadapt_mma_kernel<<<nblocks, NTHREADS, SMEM_BYTES>>>(k, rot, scales, cent, out);
}

// round 6
// speedup vs baseline: 1.9211x; 1.0565x over previous
#include <cuda_runtime.h>
#include <cstdint>

#define DD 128
#define ROWS_ITER 256        // rows per CTA iteration (32 per warp)
#define ITERS 2              // iterations per CTA -> 512 rows/CTA
#define NTHREADS 256

// ---- smem byte offsets ----
#define SM_B1HI 0            // R hi, fragment-packed
#define SM_B1LO 65536        // R lo
#define SM_ZI   131072       // indices: 256 rows x 132 bytes
#define SM_NRM  164864       // 256 f32
#define SM_INV  165888       // 256 f32
#define SM_SCL  166912       // 128 f32
#define SM_ISCL 167424       // 128 f32
#define SMEM_BYTES 167936

__device__ __forceinline__ uint32_t tf32u(float x) {
    uint32_t r;
    asm("cvt.rna.tf32.f32 %0, %1;" : "=r"(r) : "f"(x));
    return r;
}

__device__ __forceinline__ void mma8(float d[4], const uint32_t a[4],
                                     uint32_t b0, uint32_t b1) {
    asm volatile(
        "mma.sync.aligned.m16n8k8.row.col.f32.tf32.tf32.f32 "
        "{%0,%1,%2,%3}, {%4,%5,%6,%7}, {%8,%9}, {%0,%1,%2,%3};"
        : "+f"(d[0]), "+f"(d[1]), "+f"(d[2]), "+f"(d[3])
        : "r"(a[0]), "r"(a[1]), "r"(a[2]), "r"(a[3]), "r"(b0), "r"(b1));
}

__device__ __forceinline__ void split4(const float f[4], uint32_t h[4], uint32_t l[4]) {
    #pragma unroll
    for (int i = 0; i < 4; ++i) {
        h[i] = tf32u(f[i]);
        l[i] = tf32u(f[i] - __uint_as_float(h[i]));
    }
}

extern "C" __global__ void __launch_bounds__(NTHREADS, 1)
rotadapt_mma_kernel(const float* __restrict__ k,
                    const float* __restrict__ rot,
                    const float* __restrict__ scales,
                    const float* __restrict__ cent,
                    float* __restrict__ out)
{
    extern __shared__ char sb[];
    float* sclp  = (float*)(sb + SM_SCL);
    float* isclp = (float*)(sb + SM_ISCL);
    float* nrmp  = (float*)(sb + SM_NRM);
    float* invp  = (float*)(sb + SM_INV);

    const int tid  = threadIdx.x;
    const int lane = tid & 31, w = tid >> 5;
    const int g = lane >> 2, t = lane & 3;
    // warp owns rows [32w, 32w+32): two m16 tiles
    const int rA = 32 * w + g;       // tile0 rows rA, rA+8
    const int rB = rA + 16;          // tile1 rows rB, rB+8

    // ---- prologue: pack R into hi/lo fragment layout ----
    for (int idx = tid; idx < DD * DD; idx += NTHREADS) {
        int j = idx >> 7, i = idx & 127;
        float v = rot[idx];
        uint32_t hu = tf32u(v);
        uint32_t lu = tf32u(v - __uint_as_float(hu));
        int fi = (((i >> 3) * 16 + (j >> 3)) * 32 + (j & 7) * 4 + (i & 3)) * 2
                 + ((i >> 2) & 1);
        ((uint32_t*)(sb + SM_B1HI))[fi] = hu;
        ((uint32_t*)(sb + SM_B1LO))[fi] = lu;
    }
    if (tid < DD) {
        float s = scales[tid];
        sclp[tid]  = s;
        isclp[tid] = 1.0f / fmaxf(s, 1e-6f);
    }

    float bn[7];
    #pragma unroll
    for (int q = 0; q < 7; ++q) bn[q] = 0.5f * (cent[q] + cent[q + 1]);
    const float ccv = cent[lane & 7];

    const float2* bh2 = (const float2*)(sb + SM_B1HI);
    const float2* bl2 = (const float2*)(sb + SM_B1LO);
    const float*  bhf = (const float*)(sb + SM_B1HI);
    char* zi = sb + SM_ZI;

    const long ctabase = (long)blockIdx.x * (ROWS_ITER * ITERS);

    for (int tt = 0; tt < ITERS; ++tt) {
        const long rowbase = ctabase + (long)tt * ROWS_ITER;
        __syncthreads();   // protect nrm/inv smem reuse across iterations

        // ---- phase A: row norms, coalesced (4 contiguous rows per pass) ----
        {
            const int sub = lane >> 3, c8 = lane & 7;
            #pragma unroll
            for (int p = 0; p < 8; ++p) {
                int row = 32 * w + 4 * p + sub;
                const float4* kp = (const float4*)(k + (rowbase + row) * (long)DD);
                float ssq = 0.0f;
                #pragma unroll
                for (int ci = 0; ci < 4; ++ci) {
                    float4 v = kp[ci * 8 + c8];
                    ssq += v.x * v.x + v.y * v.y + v.z * v.z + v.w * v.w;
                }
                ssq += __shfl_xor_sync(0xffffffffu, ssq, 1);
                ssq += __shfl_xor_sync(0xffffffffu, ssq, 2);
                ssq += __shfl_xor_sync(0xffffffffu, ssq, 4);
                if (c8 == 0) {
                    float nr = sqrtf(ssq);
                    nrmp[row] = nr;
                    invp[row] = 1.0f / (nr + 1e-10f);
                }
            }
        }
        __syncwarp();
        // per-thread register copies of this warp's norms (rows are warp-private)
        float invA0 = invp[rA],      invA1 = invp[rA + 8];
        float invB0 = invp[rB],      invB1 = invp[rB + 8];
        float nrmA0 = nrmp[rA],      nrmA1 = nrmp[rA + 8];
        float nrmB0 = nrmp[rB],      nrmB1 = nrmp[rB + 8];

        // ---- GEMM1 (3-pass tf32), 2 row-tiles share each B fragment ----
        float acc[2][16][4];
        #pragma unroll
        for (int i = 0; i < 2; ++i)
            #pragma unroll
            for (int nt = 0; nt < 16; ++nt)
                #pragma unroll
                for (int p = 0; p < 4; ++p) acc[i][nt][p] = 0.0f;

        {
            const float* kA0 = k + (rowbase + rA) * (long)DD;
            const float* kA1 = kA0 + 8 * DD;
            const float* kB0 = kA0 + 16 * DD;
            const float* kB1 = kA0 + 24 * DD;
            #pragma unroll 2
            for (int ks = 0; ks < 16; ++ks) {
                float fA[4] = { kA0[8 * ks + t] * invA0, kA1[8 * ks + t] * invA1,
                                kA0[8 * ks + t + 4] * invA0, kA1[8 * ks + t + 4] * invA1 };
                float fB[4] = { kB0[8 * ks + t] * invB0, kB1[8 * ks + t] * invB1,
                                kB0[8 * ks + t + 4] * invB0, kB1[8 * ks + t + 4] * invB1 };
                uint32_t ahA[4], alA[4], ahB[4], alB[4];
                split4(fA, ahA, alA);
                split4(fB, ahB, alB);
                #pragma unroll
                for (int nt = 0; nt < 16; ++nt) {
                    int fi = (ks * 16 + nt) * 32 + lane;
                    float2 bh = bh2[fi];
                    float2 bl = bl2[fi];
                    uint32_t bh0 = __float_as_uint(bh.x), bh1 = __float_as_uint(bh.y);
                    uint32_t bl0 = __float_as_uint(bl.x), bl1 = __float_as_uint(bl.y);
                    mma8(acc[0][nt], ahA, bh0, bh1);
                    mma8(acc[0][nt], alA, bh0, bh1);
                    mma8(acc[0][nt], ahA, bl0, bl1);
                    mma8(acc[1][nt], ahB, bh0, bh1);
                    mma8(acc[1][nt], alB, bh0, bh1);
                    mma8(acc[1][nt], ahB, bl0, bl1);
                }
            }
        }

        // ---- prefetch next iteration's k into L1 ----
        if (tt + 1 < ITERS) {
            const char* np = (const char*)(k + (rowbase + ROWS_ITER) * (long)DD);
            #pragma unroll
            for (int pf = 0; pf < 4; ++pf)
                asm volatile("prefetch.global.L1 [%0];"
                             :: "l"(np + (pf * NTHREADS + tid) * 128));
        }

        // ---- epilogue 1: scale -> bucketize -> 8-bit indices to smem ----
        {
            const float2* scl2 = (const float2*)(sb + SM_SCL);
            #pragma unroll
            for (int i = 0; i < 2; ++i) {
                int ra = rA + 16 * i, rb = ra + 8;
                #pragma unroll
                for (int nt = 0; nt < 16; ++nt) {
                    float2 sc = scl2[(8 * nt + 2 * t) >> 1];
                    float f0 = acc[i][nt][0] * sc.x, f1 = acc[i][nt][1] * sc.y;
                    float f2 = acc[i][nt][2] * sc.x, f3 = acc[i][nt][3] * sc.y;
                    int i0 = 0, i1 = 0, i2 = 0, i3 = 0;
                    #pragma unroll
                    for (int q = 0; q < 7; ++q) {
                        i0 += (f0 > bn[q]); i1 += (f1 > bn[q]);
                        i2 += (f2 > bn[q]); i3 += (f3 > bn[q]);
                    }
                    *(uint16_t*)(zi + ra * 132 + 8 * nt + 2 * t) = (uint16_t)(i0 | (i1 << 8));
                    *(uint16_t*)(zi + rb * 132 + 8 * nt + 2 * t) = (uint16_t)(i2 | (i3 << 8));
                }
            }
        }
        __syncwarp();   // ZI rows are warp-private

        // ---- GEMM2 (2-pass tf32), shared B fragments across both row-tiles ----
        float acc2[2][16][4];
        #pragma unroll
        for (int i = 0; i < 2; ++i)
            #pragma unroll
            for (int nt = 0; nt < 16; ++nt)
                #pragma unroll
                for (int p = 0; p < 4; ++p) acc2[i][nt][p] = 0.0f;

        {
            #pragma unroll 2
            for (int ks = 0; ks < 16; ++ks) {
                float is0 = isclp[8 * ks + t], is1 = isclp[8 * ks + t + 4];
                uint32_t zhA[4], zlA[4], zhB[4], zlB[4];
                {
                    uint32_t wa = *(const uint32_t*)(zi + rA * 132 + 8 * ks);
                    uint32_t wb = *(const uint32_t*)(zi + rA * 132 + 8 * ks + 4);
                    uint32_t wc = *(const uint32_t*)(zi + (rA + 8) * 132 + 8 * ks);
                    uint32_t wd = *(const uint32_t*)(zi + (rA + 8) * 132 + 8 * ks + 4);
                    int sh = 8 * t;
                    float fz[4] = {
                        __shfl_sync(0xffffffffu, ccv, (wa >> sh) & 0xff) * is0,
                        __shfl_sync(0xffffffffu, ccv, (wc >> sh) & 0xff) * is0,
                        __shfl_sync(0xffffffffu, ccv, (wb >> sh) & 0xff) * is1,
                        __shfl_sync(0xffffffffu, ccv, (wd >> sh) & 0xff) * is1 };
                    split4(fz, zhA, zlA);
                }
                {
                    uint32_t wa = *(const uint32_t*)(zi + rB * 132 + 8 * ks);
                    uint32_t wb = *(const uint32_t*)(zi + rB * 132 + 8 * ks + 4);
                    uint32_t wc = *(const uint32_t*)(zi + (rB + 8) * 132 + 8 * ks);
                    uint32_t wd = *(const uint32_t*)(zi + (rB + 8) * 132 + 8 * ks + 4);
                    int sh = 8 * t;
                    float fz[4] = {
                        __shfl_sync(0xffffffffu, ccv, (wa >> sh) & 0xff) * is0,
                        __shfl_sync(0xffffffffu, ccv, (wc >> sh) & 0xff) * is0,
                        __shfl_sync(0xffffffffu, ccv, (wb >> sh) & 0xff) * is1,
                        __shfl_sync(0xffffffffu, ccv, (wd >> sh) & 0xff) * is1 };
                    split4(fz, zhB, zlB);
                }
                #pragma unroll
                for (int nt = 0; nt < 16; ++nt) {
                    int base = ((nt * 16 + ks) * 32 + t * 4 + (g & 3)) * 2 + (g >> 2);
                    uint32_t b0 = __float_as_uint(bhf[base]);
                    uint32_t b1 = __float_as_uint(bhf[base + 32]);
                    mma8(acc2[0][nt], zhA, b0, b1);
                    mma8(acc2[0][nt], zlA, b0, b1);
                    mma8(acc2[1][nt], zhB, b0, b1);
                    mma8(acc2[1][nt], zlB, b0, b1);
                }
            }
        }

        // ---- epilogue 2: x norm, store ----
        #pragma unroll
        for (int i = 0; i < 2; ++i) {
            float n0 = i ? nrmB0 : nrmA0;
            float n1 = i ? nrmB1 : nrmA1;
            float* o0 = out + (rowbase + rA + 16 * i) * (long)DD;
            float* o1 = o0 + 8 * DD;
            #pragma unroll
            for (int nt = 0; nt < 16; ++nt) {
                int c = 8 * nt + 2 * t;
                *(float2*)(o0 + c) = make_float2(acc2[i][nt][0] * n0, acc2[i][nt][1] * n0);
                *(float2*)(o1 + c) = make_float2(acc2[i][nt][2] * n1, acc2[i][nt][3] * n1);
            }
        }
    }
}

extern "C" void kernel_launch(void* const* d_in, const int* in_sizes, int n_in,
                              void* d_out, int out_size) {
    const float* k      = (const float*)d_in[0];
    const float* rot    = (const float*)d_in[1];
    const float* scales = (const float*)d_in[2];
    const float* cent   = (const float*)d_in[3];
    float* out = (float*)d_out;

    int nrows = in_sizes[0] / DD;
    int nblocks = nrows / (ROWS_ITER * ITERS);   // 1048576 / 512 = 2048

    cudaFuncSetAttribute(rotadapt_mma_kernel,
                         cudaFuncAttributeMaxDynamicSharedMemorySize, SMEM_BYTES);
    rotadapt_mma_kernel<<<nblocks, NTHREADS, SMEM_BYTES>>>(k, rot, scales, cent, out);
}

// round 7
// speedup vs baseline: 2.0045x; 1.0434x over previous
#include <cuda_runtime.h>
#include <cstdint>

#define DD 128
#define ROWS_ITER 256        // rows per CTA iteration (32 per warp)
#define ITERS 4              // iterations per CTA -> 1024 rows/CTA
#define NTHREADS 256

// ---- smem byte offsets ----
#define SM_B1HI 0            // R hi, fragment-packed
#define SM_B1LO 65536        // R lo
#define SM_ZI   131072       // indices: 256 rows x 132 bytes
#define SM_NRM  164864       // 256 f32
#define SM_INV  165888       // 256 f32
#define SM_SCL  166912       // 128 f32
#define SM_ISCL 167424       // 128 f32
#define SMEM_BYTES 167936

__device__ __forceinline__ uint32_t tf32u(float x) {
    uint32_t r;
    asm("cvt.rna.tf32.f32 %0, %1;" : "=r"(r) : "f"(x));
    return r;
}

__device__ __forceinline__ void mma8(float d[4], const uint32_t a[4],
                                     uint32_t b0, uint32_t b1) {
    asm volatile(
        "mma.sync.aligned.m16n8k8.row.col.f32.tf32.tf32.f32 "
        "{%0,%1,%2,%3}, {%4,%5,%6,%7}, {%8,%9}, {%0,%1,%2,%3};"
        : "+f"(d[0]), "+f"(d[1]), "+f"(d[2]), "+f"(d[3])
        : "r"(a[0]), "r"(a[1]), "r"(a[2]), "r"(a[3]), "r"(b0), "r"(b1));
}

__device__ __forceinline__ void split4(const float f[4], uint32_t h[4], uint32_t l[4]) {
    #pragma unroll
    for (int i = 0; i < 4; ++i) {
        h[i] = tf32u(f[i]);
        l[i] = tf32u(f[i] - __uint_as_float(h[i]));
    }
}

extern "C" __global__ void __launch_bounds__(NTHREADS, 1)
rotadapt_mma_kernel(const float* __restrict__ k,
                    const float* __restrict__ rot,
                    const float* __restrict__ scales,
                    const float* __restrict__ cent,
                    float* __restrict__ out)
{
    extern __shared__ char sb[];
    float* sclp  = (float*)(sb + SM_SCL);
    float* isclp = (float*)(sb + SM_ISCL);
    float* nrmp  = (float*)(sb + SM_NRM);
    float* invp  = (float*)(sb + SM_INV);

    const int tid  = threadIdx.x;
    const int lane = tid & 31, w = tid >> 5;
    const int g = lane >> 2, t = lane & 3;
    const int rA = 32 * w + g;       // tile0 rows rA, rA+8
    const int rB = rA + 16;          // tile1 rows rB, rB+8

    // ---- prologue: pack R into hi/lo fragment layout ----
    for (int idx = tid; idx < DD * DD; idx += NTHREADS) {
        int j = idx >> 7, i = idx & 127;
        float v = rot[idx];
        uint32_t hu = tf32u(v);
        uint32_t lu = tf32u(v - __uint_as_float(hu));
        int fi = (((i >> 3) * 16 + (j >> 3)) * 32 + (j & 7) * 4 + (i & 3)) * 2
                 + ((i >> 2) & 1);
        ((uint32_t*)(sb + SM_B1HI))[fi] = hu;
        ((uint32_t*)(sb + SM_B1LO))[fi] = lu;
    }
    if (tid < DD) {
        float s = scales[tid];
        sclp[tid]  = s;
        isclp[tid] = 1.0f / fmaxf(s, 1e-6f);
    }

    float bn[7];
    #pragma unroll
    for (int q = 0; q < 7; ++q) bn[q] = 0.5f * (cent[q] + cent[q + 1]);
    const float ccv = cent[lane & 7];

    __syncthreads();   // the ONLY block barrier: B tables + scales ready

    const float2* bh2 = (const float2*)(sb + SM_B1HI);
    const float2* bl2 = (const float2*)(sb + SM_B1LO);
    const float*  bhf = (const float*)(sb + SM_B1HI);
    char* zi = sb + SM_ZI;

    const long ctabase = (long)blockIdx.x * (ROWS_ITER * ITERS);

    for (int tt = 0; tt < ITERS; ++tt) {
        const long rowbase = ctabase + (long)tt * ROWS_ITER;

        // ---- phase A: row norms (warp-private rows; no block sync) ----
        {
            const int sub = lane >> 3, c8 = lane & 7;
            #pragma unroll
            for (int p = 0; p < 8; ++p) {
                int row = 32 * w + 4 * p + sub;
                const float4* kp = (const float4*)(k + (rowbase + row) * (long)DD);
                float ssq = 0.0f;
                #pragma unroll
                for (int ci = 0; ci < 4; ++ci) {
                    float4 v = kp[ci * 8 + c8];
                    ssq += v.x * v.x + v.y * v.y + v.z * v.z + v.w * v.w;
                }
                ssq += __shfl_xor_sync(0xffffffffu, ssq, 1);
                ssq += __shfl_xor_sync(0xffffffffu, ssq, 2);
                ssq += __shfl_xor_sync(0xffffffffu, ssq, 4);
                if (c8 == 0) {
                    float nr = sqrtf(ssq);
                    nrmp[row] = nr;
                    invp[row] = 1.0f / (nr + 1e-10f);
                }
            }
        }
        __syncwarp();   // also orders ZI reuse: prev GEMM2 reads < this epi1 writes
        float invA0 = invp[rA],      invA1 = invp[rA + 8];
        float invB0 = invp[rB],      invB1 = invp[rB + 8];
        float nrmA0 = nrmp[rA],      nrmA1 = nrmp[rA + 8];
        float nrmB0 = nrmp[rB],      nrmB1 = nrmp[rB + 8];

        // ---- GEMM1 (3-pass tf32), SW-pipelined A (LDG) + B (LDS) loads ----
        float acc[2][16][4];
        #pragma unroll
        for (int i = 0; i < 2; ++i)
            #pragma unroll
            for (int nt = 0; nt < 16; ++nt)
                #pragma unroll
                for (int p = 0; p < 4; ++p) acc[i][nt][p] = 0.0f;

        {
            const float* kA0 = k + (rowbase + rA) * (long)DD;
            const float* kA1 = kA0 + 8 * DD;
            const float* kB0 = kA0 + 16 * DD;
            const float* kB1 = kA0 + 24 * DD;

            float curA[4], curB[4], nxtA[4], nxtB[4];
            curA[0] = kA0[t];     curA[1] = kA1[t];
            curA[2] = kA0[t + 4]; curA[3] = kA1[t + 4];
            curB[0] = kB0[t];     curB[1] = kB1[t];
            curB[2] = kB0[t + 4]; curB[3] = kB1[t + 4];

            #pragma unroll 2
            for (int ks = 0; ks < 16; ++ks) {
                if (ks < 15) {            // prefetch next-ks A values (hides L1/L2)
                    int o = 8 * (ks + 1) + t;
                    nxtA[0] = kA0[o];     nxtA[1] = kA1[o];
                    nxtA[2] = kA0[o + 4]; nxtA[3] = kA1[o + 4];
                    nxtB[0] = kB0[o];     nxtB[1] = kB1[o];
                    nxtB[2] = kB0[o + 4]; nxtB[3] = kB1[o + 4];
                }
                float fA[4] = { curA[0] * invA0, curA[1] * invA1,
                                curA[2] * invA0, curA[3] * invA1 };
                float fB[4] = { curB[0] * invB0, curB[1] * invB1,
                                curB[2] * invB0, curB[3] * invB1 };
                uint32_t ahA[4], alA[4], ahB[4], alB[4];
                split4(fA, ahA, alA);
                split4(fB, ahB, alB);

                float2 bhb[2][4], blb[2][4];
                #pragma unroll
                for (int j = 0; j < 4; ++j) {
                    int fi = (ks * 16 + j) * 32 + lane;
                    bhb[0][j] = bh2[fi];
                    blb[0][j] = bl2[fi];
                }
                #pragma unroll
                for (int grp = 0; grp < 4; ++grp) {
                    const int cur = grp & 1, nxt = cur ^ 1;
                    if (grp < 3) {
                        #pragma unroll
                        for (int j = 0; j < 4; ++j) {
                            int fi = (ks * 16 + (grp + 1) * 4 + j) * 32 + lane;
                            bhb[nxt][j] = bh2[fi];
                            blb[nxt][j] = bl2[fi];
                        }
                    }
                    #pragma unroll
                    for (int j = 0; j < 4; ++j) {
                        int nt = grp * 4 + j;
                        uint32_t bh0 = __float_as_uint(bhb[cur][j].x);
                        uint32_t bh1 = __float_as_uint(bhb[cur][j].y);
                        uint32_t bl0 = __float_as_uint(blb[cur][j].x);
                        uint32_t bl1 = __float_as_uint(blb[cur][j].y);
                        mma8(acc[0][nt], ahA, bh0, bh1);
                        mma8(acc[0][nt], alA, bh0, bh1);
                        mma8(acc[0][nt], ahA, bl0, bl1);
                        mma8(acc[1][nt], ahB, bh0, bh1);
                        mma8(acc[1][nt], alB, bh0, bh1);
                        mma8(acc[1][nt], ahB, bl0, bl1);
                    }
                }
                #pragma unroll
                for (int i = 0; i < 4; ++i) { curA[i] = nxtA[i]; curB[i] = nxtB[i]; }
            }
        }

        // ---- prefetch next iteration's k toward L2 ----
        if (tt + 1 < ITERS) {
            const char* np = (const char*)(k + (rowbase + ROWS_ITER) * (long)DD);
            #pragma unroll
            for (int pf = 0; pf < 4; ++pf)
                asm volatile("prefetch.global.L2 [%0];"
                             :: "l"(np + (pf * NTHREADS + tid) * 128));
        }

        // ---- epilogue 1: scale -> bucketize -> 8-bit indices to smem ----
        {
            const float2* scl2 = (const float2*)(sb + SM_SCL);
            #pragma unroll
            for (int i = 0; i < 2; ++i) {
                int ra = rA + 16 * i, rb = ra + 8;
                #pragma unroll
                for (int nt = 0; nt < 16; ++nt) {
                    float2 sc = scl2[(8 * nt + 2 * t) >> 1];
                    float f0 = acc[i][nt][0] * sc.x, f1 = acc[i][nt][1] * sc.y;
                    float f2 = acc[i][nt][2] * sc.x, f3 = acc[i][nt][3] * sc.y;
                    int i0 = 0, i1 = 0, i2 = 0, i3 = 0;
                    #pragma unroll
                    for (int q = 0; q < 7; ++q) {
                        i0 += (f0 > bn[q]); i1 += (f1 > bn[q]);
                        i2 += (f2 > bn[q]); i3 += (f3 > bn[q]);
                    }
                    *(uint16_t*)(zi + ra * 132 + 8 * nt + 2 * t) = (uint16_t)(i0 | (i1 << 8));
                    *(uint16_t*)(zi + rb * 132 + 8 * nt + 2 * t) = (uint16_t)(i2 | (i3 << 8));
                }
            }
        }
        __syncwarp();

        // ---- GEMM2 (2-pass tf32), SW-pipelined ZI + B loads ----
        float acc2[2][16][4];
        #pragma unroll
        for (int i = 0; i < 2; ++i)
            #pragma unroll
            for (int nt = 0; nt < 16; ++nt)
                #pragma unroll
                for (int p = 0; p < 4; ++p) acc2[i][nt][p] = 0.0f;

        {
            uint32_t zw[8], zwn[8];
            zw[0] = *(const uint32_t*)(zi + rA * 132);
            zw[1] = *(const uint32_t*)(zi + rA * 132 + 4);
            zw[2] = *(const uint32_t*)(zi + (rA + 8) * 132);
            zw[3] = *(const uint32_t*)(zi + (rA + 8) * 132 + 4);
            zw[4] = *(const uint32_t*)(zi + rB * 132);
            zw[5] = *(const uint32_t*)(zi + rB * 132 + 4);
            zw[6] = *(const uint32_t*)(zi + (rB + 8) * 132);
            zw[7] = *(const uint32_t*)(zi + (rB + 8) * 132 + 4);

            #pragma unroll 2
            for (int ks = 0; ks < 16; ++ks) {
                if (ks < 15) {
                    int o = 8 * (ks + 1);
                    zwn[0] = *(const uint32_t*)(zi + rA * 132 + o);
                    zwn[1] = *(const uint32_t*)(zi + rA * 132 + o + 4);
                    zwn[2] = *(const uint32_t*)(zi + (rA + 8) * 132 + o);
                    zwn[3] = *(const uint32_t*)(zi + (rA + 8) * 132 + o + 4);
                    zwn[4] = *(const uint32_t*)(zi + rB * 132 + o);
                    zwn[5] = *(const uint32_t*)(zi + rB * 132 + o + 4);
                    zwn[6] = *(const uint32_t*)(zi + (rB + 8) * 132 + o);
                    zwn[7] = *(const uint32_t*)(zi + (rB + 8) * 132 + o + 4);
                }
                float is0 = isclp[8 * ks + t], is1 = isclp[8 * ks + t + 4];
                int sh = 8 * t;
                uint32_t zhA[4], zlA[4], zhB[4], zlB[4];
                {
                    float fz[4] = {
                        __shfl_sync(0xffffffffu, ccv, (zw[0] >> sh) & 0xff) * is0,
                        __shfl_sync(0xffffffffu, ccv, (zw[2] >> sh) & 0xff) * is0,
                        __shfl_sync(0xffffffffu, ccv, (zw[1] >> sh) & 0xff) * is1,
                        __shfl_sync(0xffffffffu, ccv, (zw[3] >> sh) & 0xff) * is1 };
                    split4(fz, zhA, zlA);
                }
                {
                    float fz[4] = {
                        __shfl_sync(0xffffffffu, ccv, (zw[4] >> sh) & 0xff) * is0,
                        __shfl_sync(0xffffffffu, ccv, (zw[6] >> sh) & 0xff) * is0,
                        __shfl_sync(0xffffffffu, ccv, (zw[5] >> sh) & 0xff) * is1,
                        __shfl_sync(0xffffffffu, ccv, (zw[7] >> sh) & 0xff) * is1 };
                    split4(fz, zhB, zlB);
                }

                float b0b[2][4], b1b[2][4];
                #pragma unroll
                for (int j = 0; j < 4; ++j) {
                    int base = ((j * 16 + ks) * 32 + t * 4 + (g & 3)) * 2 + (g >> 2);
                    b0b[0][j] = bhf[base];
                    b1b[0][j] = bhf[base + 32];
                }
                #pragma unroll
                for (int grp = 0; grp < 4; ++grp) {
                    const int cur = grp & 1, nxt = cur ^ 1;
                    if (grp < 3) {
                        #pragma unroll
                        for (int j = 0; j < 4; ++j) {
                            int nt2 = (grp + 1) * 4 + j;
                            int base = ((nt2 * 16 + ks) * 32 + t * 4 + (g & 3)) * 2 + (g >> 2);
                            b0b[nxt][j] = bhf[base];
                            b1b[nxt][j] = bhf[base + 32];
                        }
                    }
                    #pragma unroll
                    for (int j = 0; j < 4; ++j) {
                        int nt = grp * 4 + j;
                        uint32_t b0 = __float_as_uint(b0b[cur][j]);
                        uint32_t b1 = __float_as_uint(b1b[cur][j]);
                        mma8(acc2[0][nt], zhA, b0, b1);
                        mma8(acc2[0][nt], zlA, b0, b1);
                        mma8(acc2[1][nt], zhB, b0, b1);
                        mma8(acc2[1][nt], zlB, b0, b1);
                    }
                }
                #pragma unroll
                for (int i = 0; i < 8; ++i) zw[i] = zwn[i];
            }
        }

        // ---- epilogue 2: x norm, store ----
        #pragma unroll
        for (int i = 0; i < 2; ++i) {
            float n0 = i ? nrmB0 : nrmA0;
            float n1 = i ? nrmB1 : nrmA1;
            float* o0 = out + (rowbase + rA + 16 * i) * (long)DD;
            float* o1 = o0 + 8 * DD;
            #pragma unroll
            for (int nt = 0; nt < 16; ++nt) {
                int c = 8 * nt + 2 * t;
                *(float2*)(o0 + c) = make_float2(acc2[i][nt][0] * n0, acc2[i][nt][1] * n0);
                *(float2*)(o1 + c) = make_float2(acc2[i][nt][2] * n1, acc2[i][nt][3] * n1);
            }
        }
    }
}

extern "C" void kernel_launch(void* const* d_in, const int* in_sizes, int n_in,
                              void* d_out, int out_size) {
    const float* k      = (const float*)d_in[0];
    const float* rot    = (const float*)d_in[1];
    const float* scales = (const float*)d_in[2];
    const float* cent   = (const float*)d_in[3];
    float* out = (float*)d_out;

    int nrows = in_sizes[0] / DD;
    int nblocks = nrows / (ROWS_ITER * ITERS);   // 1048576 / 1024 = 1024

    cudaFuncSetAttribute(rotadapt_mma_kernel,
                         cudaFuncAttributeMaxDynamicSharedMemorySize, SMEM_BYTES);
    rotadapt_mma_kernel<<<nblocks, NTHREADS, SMEM_BYTES>>>(k, rot, scales, cent, out);
}